// round 2
// baseline (speedup 1.0000x reference)
#include <cuda_runtime.h>

namespace {

constexpr int T_STEPS = 512;
constexpr int TILE_B  = 16;
constexpr int THREADS = 256;
constexpr int GRID    = 2048 / TILE_B;   // 128 CTAs

typedef unsigned long long ull;

struct SM {
  float4 W1T[64 * 64];    // [k][u] -> gates (i,f,g,o) of Whh0^T          64 KB
  float4 W2T[128 * 64];   // [k][u] -> gates of [Wih1; Whh1]^T           128 KB
  float  hcat[4 * 128 * 4]; // [sub][row][4]: sub=2G+s batch quads        8 KB
  ull    Gbuf[8 * 256];   // partial-sum exchange (f32x2 pairs)          16 KB
  float  xbuf[64 * 16];   // x chunk, transposed: [t][b]                  4 KB
  float4 wih0g[64];       // Wih0 gate-interleaved per unit
  float4 bs0[64];         // bih0+bhh0 gate-interleaved
  float4 bs1[64];
  float  fcWs[64];
};

__device__ __forceinline__ ull pack2(float a, float b) {
  ull r; asm("mov.b64 %0, {%1,%2};" : "=l"(r) : "f"(a), "f"(b)); return r;
}
__device__ __forceinline__ float2 unpack2(ull p) {
  float2 r; asm("mov.b64 {%0,%1}, %2;" : "=f"(r.x), "=f"(r.y) : "l"(p)); return r;
}
__device__ __forceinline__ void fma2(ull& d, ull a, ull b) {
  asm("fma.rn.f32x2 %0, %1, %2, %0;" : "+l"(d) : "l"(a), "l"(b));
}
__device__ __forceinline__ ull add2(ull a, ull b) {
  ull r; asm("add.rn.f32x2 %0, %1, %2;" : "=l"(r) : "l"(a), "l"(b)); return r;
}

__device__ __forceinline__ float sigf(float v) {
  return __fdividef(1.0f, 1.0f + __expf(-v));   // saturation safe
}
__device__ __forceinline__ float tanhfa(float v) {
  return 2.0f * __fdividef(1.0f, 1.0f + __expf(-2.0f * v)) - 1.0f;
}

}  // namespace

__global__ void __launch_bounds__(THREADS, 1) lstm2_kernel(
    const float* __restrict__ x,
    const float* __restrict__ Wih0, const float* __restrict__ Whh0,
    const float* __restrict__ bih0, const float* __restrict__ bhh0,
    const float* __restrict__ Wih1, const float* __restrict__ Whh1,
    const float* __restrict__ bih1, const float* __restrict__ bhh1,
    const float* __restrict__ fcW,  const float* __restrict__ fcb,
    float* __restrict__ out)
{
  extern __shared__ char smraw[];
  SM* S = reinterpret_cast<SM*>(smraw);
  const int tid = threadIdx.x;
  const int u   = tid & 63;          // hidden unit
  const int s   = (tid >> 6) & 1;    // k-half
  const int G   = tid >> 7;          // batch group of 8
  const int bBase = blockIdx.x * TILE_B;

  float* W1Tf = reinterpret_cast<float*>(S->W1T);
  float* W2Tf = reinterpret_cast<float*>(S->W2T);

  // ---- stage weights (transposed, gate-interleaved) ----
  for (int idx = tid; idx < 256 * 64; idx += THREADS) {
    int j = idx >> 6, k = idx & 63;
    W1Tf[(k * 64 + (j & 63)) * 4 + (j >> 6)] = Whh0[idx];
  }
  for (int idx = tid; idx < 256 * 128; idx += THREADS) {
    int j = idx >> 7, k = idx & 127;
    float w = (k < 64) ? Wih1[j * 64 + k] : Whh1[j * 64 + (k - 64)];
    W2Tf[(k * 64 + (j & 63)) * 4 + (j >> 6)] = w;
  }
  {
    int j = tid, g = j >> 6, uu = j & 63;
    reinterpret_cast<float*>(S->wih0g)[uu * 4 + g] = Wih0[j];
    reinterpret_cast<float*>(S->bs0)[uu * 4 + g]   = bih0[j] + bhh0[j];
    reinterpret_cast<float*>(S->bs1)[uu * 4 + g]   = bih1[j] + bhh1[j];
  }
  if (tid < 64) S->fcWs[tid] = fcW[tid];
  for (int idx = tid; idx < 4 * 128 * 4; idx += THREADS) S->hcat[idx] = 0.0f;
  __syncthreads();

  // loop-invariant f32x2 constants
  const float4 wx = S->wih0g[u];
  const ull wxd[4] = {pack2(wx.x, wx.x), pack2(wx.y, wx.y),
                      pack2(wx.z, wx.z), pack2(wx.w, wx.w)};
  const float4 b0 = S->bs0[u];
  const ull bd0[4] = {pack2(b0.x, b0.x), pack2(b0.y, b0.y),
                      pack2(b0.z, b0.z), pack2(b0.w, b0.w)};
  const float4 b1 = S->bs1[u];
  const ull bd1[4] = {pack2(b1.x, b1.x), pack2(b1.y, b1.y),
                      pack2(b1.z, b1.z), pack2(b1.w, b1.w)};

  float c1[4] = {0.f, 0.f, 0.f, 0.f};
  float c2[4] = {0.f, 0.f, 0.f, 0.f};

  const int wslot = (G << 7) | ((1 - s) << 6) | u;  // partner's tid
  const int sub   = 2 * G + s;                      // my kept batch quad
  const int offk  = s ? 2 : 0;                      // kept bpair offset
  const int offs_ = s ? 0 : 2;                      // sent bpair offset

  for (int t = 0; t < T_STEPS; ++t) {
    if ((t & 63) == 0) {
      // stage + transpose 64 timesteps of x for all 16 batches
      int bb = tid >> 4, tq = tid & 15;
      float4 v = *reinterpret_cast<const float4*>(
          x + (size_t)(bBase + bb) * T_STEPS + t + tq * 4);
      S->xbuf[(tq * 4 + 0) * 16 + bb] = v.x;
      S->xbuf[(tq * 4 + 1) * 16 + bb] = v.y;
      S->xbuf[(tq * 4 + 2) * 16 + bb] = v.z;
      S->xbuf[(tq * 4 + 3) * 16 + bb] = v.w;
      __syncthreads();
    }
    const int tm = t & 63;

    // ===== layer 1 matvec: g1 = Whh0 * h1_{t-1}  (f32x2, k-half per thread)
    ull acc[4][4];
#pragma unroll
    for (int g = 0; g < 4; ++g)
#pragma unroll
      for (int bp = 0; bp < 4; ++bp) acc[g][bp] = 0ull;

    {
      const int k0 = s * 32;
#pragma unroll 8
      for (int kk = 0; kk < 32; ++kk) {
        int k = k0 + kk;
        float4 w = S->W1T[(k << 6) + u];
        ull wd[4] = {pack2(w.x, w.x), pack2(w.y, w.y),
                     pack2(w.z, w.z), pack2(w.w, w.w)};
        const ulonglong2 hA = *reinterpret_cast<const ulonglong2*>(
            S->hcat + (((2 * G) * 128 + k) << 2));
        const ulonglong2 hB = *reinterpret_cast<const ulonglong2*>(
            S->hcat + (((2 * G + 1) * 128 + k) << 2));
        ull hp[4] = {hA.x, hA.y, hB.x, hB.y};
#pragma unroll
        for (int g = 0; g < 4; ++g)
#pragma unroll
          for (int bp = 0; bp < 4; ++bp) fma2(acc[g][bp], wd[g], hp[bp]);
      }
    }

    // ----- gate phase 1 (layer 1) -----
    {
#pragma unroll
      for (int g = 0; g < 4; ++g)
#pragma unroll
        for (int j = 0; j < 2; ++j)
          S->Gbuf[(g * 2 + j) * 256 + wslot] = acc[g][offs_ + j];
      __syncthreads();

      ull tot[4][2];
#pragma unroll
      for (int g = 0; g < 4; ++g)
#pragma unroll
        for (int j = 0; j < 2; ++j)
          tot[g][j] = add2(acc[g][offk + j], S->Gbuf[(g * 2 + j) * 256 + tid]);

      const ulonglong2 xv2 = *reinterpret_cast<const ulonglong2*>(
          S->xbuf + tm * 16 + 8 * G + 4 * s);
      ull xp[2] = {xv2.x, xv2.y};
#pragma unroll
      for (int g = 0; g < 4; ++g)
#pragma unroll
        for (int j = 0; j < 2; ++j) {
          fma2(tot[g][j], wxd[g], xp[j]);
          tot[g][j] = add2(tot[g][j], bd0[g]);
        }

      float hnew[4];
#pragma unroll
      for (int j = 0; j < 2; ++j) {
        float2 gi = unpack2(tot[0][j]);
        float2 gf = unpack2(tot[1][j]);
        float2 gc = unpack2(tot[2][j]);
        float2 go = unpack2(tot[3][j]);
        {
          float iv = sigf(gi.x), fv = sigf(gf.x), gv = tanhfa(gc.x), ov = sigf(go.x);
          float cn = fv * c1[2 * j] + iv * gv;
          c1[2 * j] = cn; hnew[2 * j] = ov * tanhfa(cn);
        }
        {
          float iv = sigf(gi.y), fv = sigf(gf.y), gv = tanhfa(gc.y), ov = sigf(go.y);
          float cn = fv * c1[2 * j + 1] + iv * gv;
          c1[2 * j + 1] = cn; hnew[2 * j + 1] = ov * tanhfa(cn);
        }
      }
      *reinterpret_cast<float4*>(S->hcat + ((sub * 128 + u) << 2)) =
          make_float4(hnew[0], hnew[1], hnew[2], hnew[3]);
      __syncthreads();
    }

    // ===== layer 2 matvec: g2 = [Wih1;Whh1] * [h1_t ; h2_{t-1}]
#pragma unroll
    for (int g = 0; g < 4; ++g)
#pragma unroll
      for (int bp = 0; bp < 4; ++bp) acc[g][bp] = 0ull;

    {
      const int k0 = s * 64;
#pragma unroll 8
      for (int kk = 0; kk < 64; ++kk) {
        int k = k0 + kk;
        float4 w = S->W2T[(k << 6) + u];
        ull wd[4] = {pack2(w.x, w.x), pack2(w.y, w.y),
                     pack2(w.z, w.z), pack2(w.w, w.w)};
        const ulonglong2 hA = *reinterpret_cast<const ulonglong2*>(
            S->hcat + (((2 * G) * 128 + k) << 2));
        const ulonglong2 hB = *reinterpret_cast<const ulonglong2*>(
            S->hcat + (((2 * G + 1) * 128 + k) << 2));
        ull hp[4] = {hA.x, hA.y, hB.x, hB.y};
#pragma unroll
        for (int g = 0; g < 4; ++g)
#pragma unroll
          for (int bp = 0; bp < 4; ++bp) fma2(acc[g][bp], wd[g], hp[bp]);
      }
    }

    // ----- gate phase 2 (layer 2) -----
    {
#pragma unroll
      for (int g = 0; g < 4; ++g)
#pragma unroll
        for (int j = 0; j < 2; ++j)
          S->Gbuf[(g * 2 + j) * 256 + wslot] = acc[g][offs_ + j];
      __syncthreads();

      ull tot[4][2];
#pragma unroll
      for (int g = 0; g < 4; ++g)
#pragma unroll
        for (int j = 0; j < 2; ++j) {
          tot[g][j] = add2(acc[g][offk + j], S->Gbuf[(g * 2 + j) * 256 + tid]);
          tot[g][j] = add2(tot[g][j], bd1[g]);
        }

      float hnew[4];
#pragma unroll
      for (int j = 0; j < 2; ++j) {
        float2 gi = unpack2(tot[0][j]);
        float2 gf = unpack2(tot[1][j]);
        float2 gc = unpack2(tot[2][j]);
        float2 go = unpack2(tot[3][j]);
        {
          float iv = sigf(gi.x), fv = sigf(gf.x), gv = tanhfa(gc.x), ov = sigf(go.x);
          float cn = fv * c2[2 * j] + iv * gv;
          c2[2 * j] = cn; hnew[2 * j] = ov * tanhfa(cn);
        }
        {
          float iv = sigf(gi.y), fv = sigf(gf.y), gv = tanhfa(gc.y), ov = sigf(go.y);
          float cn = fv * c2[2 * j + 1] + iv * gv;
          c2[2 * j + 1] = cn; hnew[2 * j + 1] = ov * tanhfa(cn);
        }
      }
      *reinterpret_cast<float4*>(S->hcat + ((sub * 128 + 64 + u) << 2)) =
          make_float4(hnew[0], hnew[1], hnew[2], hnew[3]);
      __syncthreads();
    }
  }

  // ===== FC epilogue: out[b] = fcW . h2_{T-1} + fcb =====
  if (tid < TILE_B) {
    float accO = fcb[0];
#pragma unroll 8
    for (int uu = 0; uu < 64; ++uu)
      accO += S->fcWs[uu] * S->hcat[(((tid >> 2) * 128 + 64 + uu) << 2) + (tid & 3)];
    out[bBase + tid] = accO;
  }
}

extern "C" void kernel_launch(void* const* d_in, const int* in_sizes, int n_in,
                              void* d_out, int out_size) {
  (void)in_sizes; (void)n_in; (void)out_size;
  cudaFuncSetAttribute(lstm2_kernel,
                       cudaFuncAttributeMaxDynamicSharedMemorySize,
                       (int)sizeof(SM));
  lstm2_kernel<<<GRID, THREADS, sizeof(SM)>>>(
      (const float*)d_in[0],
      (const float*)d_in[1], (const float*)d_in[2],
      (const float*)d_in[3], (const float*)d_in[4],
      (const float*)d_in[5], (const float*)d_in[6],
      (const float*)d_in[7], (const float*)d_in[8],
      (const float*)d_in[9], (const float*)d_in[10],
      (float*)d_out);
}

// round 3
// speedup vs baseline: 1.0020x; 1.0020x over previous
#include <cuda_runtime.h>

namespace {

constexpr int T_STEPS = 512;
constexpr int TILE_B  = 16;
constexpr int THREADS = 256;
constexpr int GRID    = 2048 / TILE_B;   // 128 CTAs

typedef unsigned long long ull;

struct SM {
  float4 W1T[64 * 64];    // [k][u] -> gates (i,f,g,o) of Whh0^T          64 KB
  float4 W2T[128 * 64];   // [k][u] -> gates of [Wih1; Whh1]^T           128 KB
  float  hcat[4 * 128 * 4]; // [sub][row][4]: sub=2G+s batch quads        8 KB
  ull    Gbuf[8 * 256];   // partial-sum exchange (f32x2 pairs)          16 KB
  float  xbuf[64 * 16];   // x chunk, transposed: [t][b]                  4 KB
  float4 wih0g[64];       // Wih0 gate-interleaved per unit
  float4 bs0[64];         // bih0+bhh0 gate-interleaved
  float4 bs1[64];
  float  fcWs[64];
};

__device__ __forceinline__ ull pack2(float a, float b) {
  ull r; asm("mov.b64 %0, {%1,%2};" : "=l"(r) : "f"(a), "f"(b)); return r;
}
__device__ __forceinline__ float2 unpack2(ull p) {
  float2 r; asm("mov.b64 {%0,%1}, %2;" : "=f"(r.x), "=f"(r.y) : "l"(p)); return r;
}
__device__ __forceinline__ void fma2(ull& d, ull a, ull b) {
  asm("fma.rn.f32x2 %0, %1, %2, %0;" : "+l"(d) : "l"(a), "l"(b));
}
__device__ __forceinline__ ull add2(ull a, ull b) {
  ull r; asm("add.rn.f32x2 %0, %1, %2;" : "=l"(r) : "l"(a), "l"(b)); return r;
}

__device__ __forceinline__ float sigf(float v) {
  return __fdividef(1.0f, 1.0f + __expf(-v));   // saturation safe
}
__device__ __forceinline__ float tanhfa(float v) {
  return 2.0f * __fdividef(1.0f, 1.0f + __expf(-2.0f * v)) - 1.0f;
}

}  // namespace

__global__ void __launch_bounds__(THREADS, 1) lstm2_kernel(
    const float* __restrict__ x,
    const float* __restrict__ Wih0, const float* __restrict__ Whh0,
    const float* __restrict__ bih0, const float* __restrict__ bhh0,
    const float* __restrict__ Wih1, const float* __restrict__ Whh1,
    const float* __restrict__ bih1, const float* __restrict__ bhh1,
    const float* __restrict__ fcW,  const float* __restrict__ fcb,
    float* __restrict__ out)
{
  extern __shared__ char smraw[];
  SM* S = reinterpret_cast<SM*>(smraw);
  const int tid = threadIdx.x;
  const int u   = tid & 63;          // hidden unit
  const int s   = (tid >> 6) & 1;    // k-half
  const int G   = tid >> 7;          // batch group of 8
  const int bBase = blockIdx.x * TILE_B;

  float* W1Tf = reinterpret_cast<float*>(S->W1T);
  float* W2Tf = reinterpret_cast<float*>(S->W2T);

  // ---- stage weights (transposed, gate-interleaved) ----
  for (int idx = tid; idx < 256 * 64; idx += THREADS) {
    int j = idx >> 6, k = idx & 63;
    W1Tf[(k * 64 + (j & 63)) * 4 + (j >> 6)] = Whh0[idx];
  }
  for (int idx = tid; idx < 256 * 128; idx += THREADS) {
    int j = idx >> 7, k = idx & 127;
    float w = (k < 64) ? Wih1[j * 64 + k] : Whh1[j * 64 + (k - 64)];
    W2Tf[(k * 64 + (j & 63)) * 4 + (j >> 6)] = w;
  }
  {
    int j = tid, g = j >> 6, uu = j & 63;
    reinterpret_cast<float*>(S->wih0g)[uu * 4 + g] = Wih0[j];
    reinterpret_cast<float*>(S->bs0)[uu * 4 + g]   = bih0[j] + bhh0[j];
    reinterpret_cast<float*>(S->bs1)[uu * 4 + g]   = bih1[j] + bhh1[j];
  }
  if (tid < 64) S->fcWs[tid] = fcW[tid];
  for (int idx = tid; idx < 4 * 128 * 4; idx += THREADS) S->hcat[idx] = 0.0f;
  __syncthreads();

  // loop-invariant f32x2 constants
  const float4 wx = S->wih0g[u];
  const ull wxd[4] = {pack2(wx.x, wx.x), pack2(wx.y, wx.y),
                      pack2(wx.z, wx.z), pack2(wx.w, wx.w)};
  const float4 b0 = S->bs0[u];
  const ull bd0[4] = {pack2(b0.x, b0.x), pack2(b0.y, b0.y),
                      pack2(b0.z, b0.z), pack2(b0.w, b0.w)};
  const float4 b1 = S->bs1[u];
  const ull bd1[4] = {pack2(b1.x, b1.x), pack2(b1.y, b1.y),
                      pack2(b1.z, b1.z), pack2(b1.w, b1.w)};

  float c1[4] = {0.f, 0.f, 0.f, 0.f};
  float c2[4] = {0.f, 0.f, 0.f, 0.f};

  const int wslot = (G << 7) | ((1 - s) << 6) | u;  // partner's tid
  const int sub   = 2 * G + s;                      // my kept batch quad
  const int offk  = s ? 2 : 0;                      // kept bpair offset
  const int offs_ = s ? 0 : 2;                      // sent bpair offset

  for (int t = 0; t < T_STEPS; ++t) {
    if ((t & 63) == 0) {
      // stage + transpose 64 timesteps of x for all 16 batches
      int bb = tid >> 4, tq = tid & 15;
      float4 v = *reinterpret_cast<const float4*>(
          x + (size_t)(bBase + bb) * T_STEPS + t + tq * 4);
      S->xbuf[(tq * 4 + 0) * 16 + bb] = v.x;
      S->xbuf[(tq * 4 + 1) * 16 + bb] = v.y;
      S->xbuf[(tq * 4 + 2) * 16 + bb] = v.z;
      S->xbuf[(tq * 4 + 3) * 16 + bb] = v.w;
      __syncthreads();
    }
    const int tm = t & 63;

    // ===== layer 1 matvec: g1 = Whh0 * h1_{t-1}  (f32x2, k-half per thread)
    ull acc[4][4];
#pragma unroll
    for (int g = 0; g < 4; ++g)
#pragma unroll
      for (int bp = 0; bp < 4; ++bp) acc[g][bp] = 0ull;

    {
      const int k0 = s * 32;
#pragma unroll 8
      for (int kk = 0; kk < 32; ++kk) {
        int k = k0 + kk;
        float4 w = S->W1T[(k << 6) + u];
        ull wd[4] = {pack2(w.x, w.x), pack2(w.y, w.y),
                     pack2(w.z, w.z), pack2(w.w, w.w)};
        const ulonglong2 hA = *reinterpret_cast<const ulonglong2*>(
            S->hcat + (((2 * G) * 128 + k) << 2));
        const ulonglong2 hB = *reinterpret_cast<const ulonglong2*>(
            S->hcat + (((2 * G + 1) * 128 + k) << 2));
        ull hp[4] = {hA.x, hA.y, hB.x, hB.y};
#pragma unroll
        for (int g = 0; g < 4; ++g)
#pragma unroll
          for (int bp = 0; bp < 4; ++bp) fma2(acc[g][bp], wd[g], hp[bp]);
      }
    }

    // ----- gate phase 1 (layer 1) -----
    {
#pragma unroll
      for (int g = 0; g < 4; ++g)
#pragma unroll
        for (int j = 0; j < 2; ++j)
          S->Gbuf[(g * 2 + j) * 256 + wslot] = acc[g][offs_ + j];
      __syncthreads();

      ull tot[4][2];
#pragma unroll
      for (int g = 0; g < 4; ++g)
#pragma unroll
        for (int j = 0; j < 2; ++j)
          tot[g][j] = add2(acc[g][offk + j], S->Gbuf[(g * 2 + j) * 256 + tid]);

      const ulonglong2 xv2 = *reinterpret_cast<const ulonglong2*>(
          S->xbuf + tm * 16 + 8 * G + 4 * s);
      ull xp[2] = {xv2.x, xv2.y};
#pragma unroll
      for (int g = 0; g < 4; ++g)
#pragma unroll
        for (int j = 0; j < 2; ++j) {
          fma2(tot[g][j], wxd[g], xp[j]);
          tot[g][j] = add2(tot[g][j], bd0[g]);
        }

      float hnew[4];
#pragma unroll
      for (int j = 0; j < 2; ++j) {
        float2 gi = unpack2(tot[0][j]);
        float2 gf = unpack2(tot[1][j]);
        float2 gc = unpack2(tot[2][j]);
        float2 go = unpack2(tot[3][j]);
        {
          float iv = sigf(gi.x), fv = sigf(gf.x), gv = tanhfa(gc.x), ov = sigf(go.x);
          float cn = fv * c1[2 * j] + iv * gv;
          c1[2 * j] = cn; hnew[2 * j] = ov * tanhfa(cn);
        }
        {
          float iv = sigf(gi.y), fv = sigf(gf.y), gv = tanhfa(gc.y), ov = sigf(go.y);
          float cn = fv * c1[2 * j + 1] + iv * gv;
          c1[2 * j + 1] = cn; hnew[2 * j + 1] = ov * tanhfa(cn);
        }
      }
      *reinterpret_cast<float4*>(S->hcat + ((sub * 128 + u) << 2)) =
          make_float4(hnew[0], hnew[1], hnew[2], hnew[3]);
      __syncthreads();
    }

    // ===== layer 2 matvec: g2 = [Wih1;Whh1] * [h1_t ; h2_{t-1}]
#pragma unroll
    for (int g = 0; g < 4; ++g)
#pragma unroll
      for (int bp = 0; bp < 4; ++bp) acc[g][bp] = 0ull;

    {
      const int k0 = s * 64;
#pragma unroll 8
      for (int kk = 0; kk < 64; ++kk) {
        int k = k0 + kk;
        float4 w = S->W2T[(k << 6) + u];
        ull wd[4] = {pack2(w.x, w.x), pack2(w.y, w.y),
                     pack2(w.z, w.z), pack2(w.w, w.w)};
        const ulonglong2 hA = *reinterpret_cast<const ulonglong2*>(
            S->hcat + (((2 * G) * 128 + k) << 2));
        const ulonglong2 hB = *reinterpret_cast<const ulonglong2*>(
            S->hcat + (((2 * G + 1) * 128 + k) << 2));
        ull hp[4] = {hA.x, hA.y, hB.x, hB.y};
#pragma unroll
        for (int g = 0; g < 4; ++g)
#pragma unroll
          for (int bp = 0; bp < 4; ++bp) fma2(acc[g][bp], wd[g], hp[bp]);
      }
    }

    // ----- gate phase 2 (layer 2) -----
    {
#pragma unroll
      for (int g = 0; g < 4; ++g)
#pragma unroll
        for (int j = 0; j < 2; ++j)
          S->Gbuf[(g * 2 + j) * 256 + wslot] = acc[g][offs_ + j];
      __syncthreads();

      ull tot[4][2];
#pragma unroll
      for (int g = 0; g < 4; ++g)
#pragma unroll
        for (int j = 0; j < 2; ++j) {
          tot[g][j] = add2(acc[g][offk + j], S->Gbuf[(g * 2 + j) * 256 + tid]);
          tot[g][j] = add2(tot[g][j], bd1[g]);
        }

      float hnew[4];
#pragma unroll
      for (int j = 0; j < 2; ++j) {
        float2 gi = unpack2(tot[0][j]);
        float2 gf = unpack2(tot[1][j]);
        float2 gc = unpack2(tot[2][j]);
        float2 go = unpack2(tot[3][j]);
        {
          float iv = sigf(gi.x), fv = sigf(gf.x), gv = tanhfa(gc.x), ov = sigf(go.x);
          float cn = fv * c2[2 * j] + iv * gv;
          c2[2 * j] = cn; hnew[2 * j] = ov * tanhfa(cn);
        }
        {
          float iv = sigf(gi.y), fv = sigf(gf.y), gv = tanhfa(gc.y), ov = sigf(go.y);
          float cn = fv * c2[2 * j + 1] + iv * gv;
          c2[2 * j + 1] = cn; hnew[2 * j + 1] = ov * tanhfa(cn);
        }
      }
      *reinterpret_cast<float4*>(S->hcat + ((sub * 128 + 64 + u) << 2)) =
          make_float4(hnew[0], hnew[1], hnew[2], hnew[3]);
      __syncthreads();
    }
  }

  // ===== FC epilogue: out[b] = fcW . h2_{T-1} + fcb =====
  if (tid < TILE_B) {
    float accO = fcb[0];
#pragma unroll 8
    for (int uu = 0; uu < 64; ++uu)
      accO += S->fcWs[uu] * S->hcat[(((tid >> 2) * 128 + 64 + uu) << 2) + (tid & 3)];
    out[bBase + tid] = accO;
  }
}

extern "C" void kernel_launch(void* const* d_in, const int* in_sizes, int n_in,
                              void* d_out, int out_size) {
  (void)in_sizes; (void)n_in; (void)out_size;
  cudaFuncSetAttribute(lstm2_kernel,
                       cudaFuncAttributeMaxDynamicSharedMemorySize,
                       (int)sizeof(SM));
  lstm2_kernel<<<GRID, THREADS, sizeof(SM)>>>(
      (const float*)d_in[0],
      (const float*)d_in[1], (const float*)d_in[2],
      (const float*)d_in[3], (const float*)d_in[4],
      (const float*)d_in[5], (const float*)d_in[6],
      (const float*)d_in[7], (const float*)d_in[8],
      (const float*)d_in[9], (const float*)d_in[10],
      (float*)d_out);
}

// round 4
// speedup vs baseline: 2.4710x; 2.4662x over previous
#include <cuda_runtime.h>
#include <cuda_bf16.h>
#include <cstdint>

namespace {
constexpr int T_STEPS = 512;
constexpr int TILE_B  = 16;
constexpr int THREADS = 256;
constexpr int GRID    = 2048 / TILE_B;

constexpr int OFF_A1H = 0;
constexpr int OFF_A1L = 32768;
constexpr int OFF_A2H = 65536;
constexpr int OFF_A2L = 131072;
constexpr int OFF_HH  = 196608;
constexpr int OFF_HL  = 196608 + 4352;
constexpr int OFF_X   = 196608 + 8704;
constexpr int SMEM_TOTAL = OFF_X + 4096;   // 209408 B
constexpr int HS = 136;                    // bf16 elems per h row (pad: conflict-free)

__device__ __forceinline__ uint32_t smem_u32(const void* p) {
  uint32_t a;
  asm("{ .reg .u64 t; cvta.to.shared.u64 t, %1; cvt.u32.u64 %0, t; }" : "=r"(a) : "l"(p));
  return a;
}
__device__ __forceinline__ void ldm4(uint32_t* r, uint32_t a) {
  asm volatile("ldmatrix.sync.aligned.m8n8.x4.shared.b16 {%0,%1,%2,%3}, [%4];"
               : "=r"(r[0]), "=r"(r[1]), "=r"(r[2]), "=r"(r[3]) : "r"(a));
}
__device__ __forceinline__ void mma_bf(float4& d, const uint4& a, uint32_t b0, uint32_t b1) {
  asm volatile("mma.sync.aligned.m16n8k16.row.col.f32.bf16.bf16.f32 "
               "{%0,%1,%2,%3}, {%4,%5,%6,%7}, {%8,%9}, {%0,%1,%2,%3};"
               : "+f"(d.x), "+f"(d.y), "+f"(d.z), "+f"(d.w)
               : "r"(a.x), "r"(a.y), "r"(a.z), "r"(a.w), "r"(b0), "r"(b1));
}
__device__ __forceinline__ uint32_t pkbf2(float lo, float hi) {
  __nv_bfloat16 l = __float2bfloat16(lo), h = __float2bfloat16(hi);
  unsigned short ls, hs;
  memcpy(&ls, &l, 2); memcpy(&hs, &h, 2);
  return (uint32_t)ls | ((uint32_t)hs << 16);
}
__device__ __forceinline__ float sigf(float v) {
  return __fdividef(1.0f, 1.0f + __expf(-v));
}
__device__ __forceinline__ float tanhfa(float v) {
  return 2.0f * __fdividef(1.0f, 1.0f + __expf(-2.0f * v)) - 1.0f;
}
}  // namespace

__global__ void __launch_bounds__(THREADS, 1) lstm2_hmma_kernel(
    const float* __restrict__ x,
    const float* __restrict__ Wih0, const float* __restrict__ Whh0,
    const float* __restrict__ bih0, const float* __restrict__ bhh0,
    const float* __restrict__ Wih1, const float* __restrict__ Whh1,
    const float* __restrict__ bih1, const float* __restrict__ bhh1,
    const float* __restrict__ fcW,  const float* __restrict__ fcb,
    float* __restrict__ out)
{
  extern __shared__ char sm[];
  const uint32_t sb = smem_u32(sm);
  const int tid = threadIdx.x, w = tid >> 5, lane = tid & 31;
  const int bBase = blockIdx.x * TILE_B;

  // ---- build A fragments (per-lane mma layout, wh/wl split), row perm:
  // mma-row R -> gate g=(R&31)>>3, unit u=(R>>5)*8+(R&7) ----
  for (int i = tid; i < 64 * 32; i += THREADS) {
    int f = i >> 5, l = i & 31;
    int mt = f >> 2, kc = f & 3;
    int p = l >> 2, c0 = (l & 3) * 2;
    float wh[8], wl[8];
#pragma unroll
    for (int e = 0; e < 8; ++e) {
      int R = mt * 16 + p + ((e >> 1) & 1) * 8;
      int k = kc * 16 + c0 + (e & 1) + (e >> 2) * 8;
      int g = (R & 31) >> 3, u = (R >> 5) * 8 + (R & 7);
      float wv = Whh0[(g * 64 + u) * 64 + k];
      __nv_bfloat16 b = __float2bfloat16(wv);
      wh[e] = __bfloat162float(b); wl[e] = wv - wh[e];
    }
    *(uint4*)(sm + OFF_A1H + (size_t)i * 16) =
        make_uint4(pkbf2(wh[0],wh[1]), pkbf2(wh[2],wh[3]), pkbf2(wh[4],wh[5]), pkbf2(wh[6],wh[7]));
    *(uint4*)(sm + OFF_A1L + (size_t)i * 16) =
        make_uint4(pkbf2(wl[0],wl[1]), pkbf2(wl[2],wl[3]), pkbf2(wl[4],wl[5]), pkbf2(wl[6],wl[7]));
  }
  for (int i = tid; i < 128 * 32; i += THREADS) {
    int f = i >> 5, l = i & 31;
    int mt = f >> 3, kc = f & 7;
    int p = l >> 2, c0 = (l & 3) * 2;
    float wh[8], wl[8];
#pragma unroll
    for (int e = 0; e < 8; ++e) {
      int R = mt * 16 + p + ((e >> 1) & 1) * 8;
      int k = kc * 16 + c0 + (e & 1) + (e >> 2) * 8;
      int g = (R & 31) >> 3, u = (R >> 5) * 8 + (R & 7);
      float wv = (k < 64) ? Wih1[(g * 64 + u) * 64 + k]
                          : Whh1[(g * 64 + u) * 64 + (k - 64)];
      __nv_bfloat16 b = __float2bfloat16(wv);
      wh[e] = __bfloat162float(b); wl[e] = wv - wh[e];
    }
    *(uint4*)(sm + OFF_A2H + (size_t)i * 16) =
        make_uint4(pkbf2(wh[0],wh[1]), pkbf2(wh[2],wh[3]), pkbf2(wh[4],wh[5]), pkbf2(wh[6],wh[7]));
    *(uint4*)(sm + OFF_A2L + (size_t)i * 16) =
        make_uint4(pkbf2(wl[0],wl[1]), pkbf2(wl[2],wl[3]), pkbf2(wl[4],wl[5]), pkbf2(wl[6],wl[7]));
  }
  // zero h buffers (hh + hl contiguous: 2*4352 B)
  for (int i = tid; i < 2176; i += THREADS)
    reinterpret_cast<uint32_t*>(sm + OFF_HH)[i] = 0u;

  // per-thread act constants: unit u, batches n = (j>>1)*8 + (lane&3)*2 + (j&1)
  const int ut = w * 8 + (lane >> 2);
  float wxr[4], b0r[4], b1r[4];
#pragma unroll
  for (int g = 0; g < 4; ++g) {
    wxr[g] = Wih0[g * 64 + ut];
    b0r[g] = bih0[g * 64 + ut] + bhh0[g * 64 + ut];
    b1r[g] = bih1[g * 64 + ut] + bhh1[g * 64 + ut];
  }
  // ldmatrix per-lane base: tile ti: n=((ti>>1)&1)*8+(lane&7), k=(ti&1)*8
  const int ti = lane >> 3;
  const uint32_t boff = (uint32_t)((((ti >> 1) & 1) * 8 + (lane & 7)) * HS + (ti & 1) * 8) * 2;
  const uint32_t bHH = sb + OFF_HH + boff;
  const uint32_t bHL = sb + OFF_HL + boff;

  float* xb = reinterpret_cast<float*>(sm + OFF_X);
  float c1[4] = {0.f,0.f,0.f,0.f}, c2[4] = {0.f,0.f,0.f,0.f};
  __syncthreads();

  uint32_t bh[8][4], bl[8][4];

  for (int t = 0; t < T_STEPS; ++t) {
    if ((t & 63) == 0) {
      int b16 = tid >> 4, tq = tid & 15;
      float4 v = *reinterpret_cast<const float4*>(
          x + (size_t)(bBase + b16) * T_STEPS + t + tq * 4);
      xb[(tq * 4 + 0) * 16 + b16] = v.x;
      xb[(tq * 4 + 1) * 16 + b16] = v.y;
      xb[(tq * 4 + 2) * 16 + b16] = v.z;
      xb[(tq * 4 + 3) * 16 + b16] = v.w;
      __syncthreads();
    }

    // ===== GEMM1: gates1 = W1 * h1_{t-1}  (K=64) =====
#pragma unroll
    for (int kc = 0; kc < 4; ++kc) { ldm4(bh[kc], bHH + kc * 32); ldm4(bl[kc], bHL + kc * 32); }
    __syncthreads();   // (a) B reads done before act1 overwrites h1

    float4 D[2][2];
#pragma unroll
    for (int mt = 0; mt < 2; ++mt)
#pragma unroll
      for (int nt = 0; nt < 2; ++nt) D[mt][nt] = make_float4(0.f,0.f,0.f,0.f);
#pragma unroll
    for (int kc = 0; kc < 4; ++kc)
#pragma unroll
      for (int mt = 0; mt < 2; ++mt) {
        uint4 ah = *(const uint4*)(sm + OFF_A1H + (size_t)(((2*w+mt)*4 + kc)*32 + lane)*16);
        uint4 al = *(const uint4*)(sm + OFF_A1L + (size_t)(((2*w+mt)*4 + kc)*32 + lane)*16);
#pragma unroll
        for (int nt = 0; nt < 2; ++nt) {
          mma_bf(D[mt][nt], ah, bh[kc][nt*2], bh[kc][nt*2+1]);
          mma_bf(D[mt][nt], ah, bl[kc][nt*2], bl[kc][nt*2+1]);
          mma_bf(D[mt][nt], al, bh[kc][nt*2], bh[kc][nt*2+1]);
        }
      }

    // ----- act1: thread owns gates(i,f,g,o) of unit ut for 4 batches -----
#pragma unroll
    for (int j = 0; j < 4; ++j) {
      int nt = j >> 1, jj = j & 1;
      int n  = nt * 8 + (lane & 3) * 2 + jj;
      float xv = xb[(t & 63) * 16 + n];
      float gi = (jj ? D[0][nt].y : D[0][nt].x) + b0r[0] + wxr[0] * xv;
      float gf = (jj ? D[0][nt].w : D[0][nt].z) + b0r[1] + wxr[1] * xv;
      float gg = (jj ? D[1][nt].y : D[1][nt].x) + b0r[2] + wxr[2] * xv;
      float go = (jj ? D[1][nt].w : D[1][nt].z) + b0r[3] + wxr[3] * xv;
      float cn = sigf(gf) * c1[j] + sigf(gi) * tanhfa(gg);
      c1[j] = cn;
      float h = sigf(go) * tanhfa(cn);
      __nv_bfloat16 hhv = __float2bfloat16(h);
      float hlf = h - __bfloat162float(hhv);
      *(__nv_bfloat16*)(sm + OFF_HH + (size_t)(n * HS + ut) * 2) = hhv;
      *(__nv_bfloat16*)(sm + OFF_HL + (size_t)(n * HS + ut) * 2) = __float2bfloat16(hlf);
    }
    __syncthreads();   // (b) h1_t visible

    // ===== GEMM2: gates2 = W2 * [h1_t ; h2_{t-1}]  (K=128) =====
#pragma unroll
    for (int kc = 0; kc < 8; ++kc) { ldm4(bh[kc], bHH + kc * 32); ldm4(bl[kc], bHL + kc * 32); }
    __syncthreads();   // (c) B reads done before act2 overwrites h2

#pragma unroll
    for (int mt = 0; mt < 2; ++mt)
#pragma unroll
      for (int nt = 0; nt < 2; ++nt) D[mt][nt] = make_float4(0.f,0.f,0.f,0.f);
#pragma unroll
    for (int kc = 0; kc < 8; ++kc)
#pragma unroll
      for (int mt = 0; mt < 2; ++mt) {
        uint4 ah = *(const uint4*)(sm + OFF_A2H + (size_t)(((2*w+mt)*8 + kc)*32 + lane)*16);
        uint4 al = *(const uint4*)(sm + OFF_A2L + (size_t)(((2*w+mt)*8 + kc)*32 + lane)*16);
#pragma unroll
        for (int nt = 0; nt < 2; ++nt) {
          mma_bf(D[mt][nt], ah, bh[kc][nt*2], bh[kc][nt*2+1]);
          mma_bf(D[mt][nt], ah, bl[kc][nt*2], bl[kc][nt*2+1]);
          mma_bf(D[mt][nt], al, bh[kc][nt*2], bh[kc][nt*2+1]);
        }
      }

    // ----- act2 -----
#pragma unroll
    for (int j = 0; j < 4; ++j) {
      int nt = j >> 1, jj = j & 1;
      int n  = nt * 8 + (lane & 3) * 2 + jj;
      float gi = (jj ? D[0][nt].y : D[0][nt].x) + b1r[0];
      float gf = (jj ? D[0][nt].w : D[0][nt].z) + b1r[1];
      float gg = (jj ? D[1][nt].y : D[1][nt].x) + b1r[2];
      float go = (jj ? D[1][nt].w : D[1][nt].z) + b1r[3];
      float cn = sigf(gf) * c2[j] + sigf(gi) * tanhfa(gg);
      c2[j] = cn;
      float h = sigf(go) * tanhfa(cn);
      __nv_bfloat16 hhv = __float2bfloat16(h);
      float hlf = h - __bfloat162float(hhv);
      *(__nv_bfloat16*)(sm + OFF_HH + (size_t)(n * HS + 64 + ut) * 2) = hhv;
      *(__nv_bfloat16*)(sm + OFF_HL + (size_t)(n * HS + 64 + ut) * 2) = __float2bfloat16(hlf);
    }
  }

  // ===== FC epilogue: out[b] = fcW . h2_{T-1} + fcb (h2 = hh+hl) =====
  __syncthreads();
  if (tid < TILE_B) {
    float acc = fcb[0];
    const __nv_bfloat16* hh = (const __nv_bfloat16*)(sm + OFF_HH);
    const __nv_bfloat16* hl = (const __nv_bfloat16*)(sm + OFF_HL);
#pragma unroll 8
    for (int u = 0; u < 64; ++u)
      acc += fcW[u] * (__bfloat162float(hh[tid * HS + 64 + u]) +
                       __bfloat162float(hl[tid * HS + 64 + u]));
    out[bBase + tid] = acc;
  }
}

extern "C" void kernel_launch(void* const* d_in, const int* in_sizes, int n_in,
                              void* d_out, int out_size) {
  (void)in_sizes; (void)n_in; (void)out_size;
  cudaFuncSetAttribute(lstm2_hmma_kernel,
                       cudaFuncAttributeMaxDynamicSharedMemorySize, SMEM_TOTAL);
  lstm2_hmma_kernel<<<GRID, THREADS, SMEM_TOTAL>>>(
      (const float*)d_in[0],
      (const float*)d_in[1], (const float*)d_in[2],
      (const float*)d_in[3], (const float*)d_in[4],
      (const float*)d_in[5], (const float*)d_in[6],
      (const float*)d_in[7], (const float*)d_in[8],
      (const float*)d_in[9], (const float*)d_in[10],
      (float*)d_out);
}